// round 14
// baseline (speedup 1.0000x reference)
#include <cuda_runtime.h>
#include <cuda_fp16.h>
#include <cstdint>
#include <math.h>

#define B_   8
#define N_   1024
#define DM_  512
#define H_   8
#define MT_  (B_ * N_)      // 8192
#define GB   18432          // 128 rows x 144 B (Q tiles in attention)

// GEMM pipeline geometry: BK=32, rows of 80 B, 4 buffers, 2 stages
#define GROW 80
#define GBUF 10240          // 128 * 80
#define GSTG 40960          // 4 * GBUF
// Attention KV stage: 3 buffers (Khi, Klo, V) x (64 rows x 144 B), 3 stages
#define KVB  9216
#define KVSTG (3 * KVB)     // 27648

// ---------------- fp16 scratch (__device__ globals; no allocs) -------------
__device__ __half g_curhi[MT_ * DM_], g_curlo[MT_ * DM_];
__device__ __half g_hidhi[MT_ * DM_], g_hidlo[MT_ * DM_];
__device__ __half g_wqThi [DM_ * DM_],     g_wqTlo [DM_ * DM_];
__device__ __half g_wkvThi[2 * DM_ * DM_], g_wkvTlo[2 * DM_ * DM_];
__device__ __half g_woT   [DM_ * DM_];
__device__ __half g_qhi[MT_ * DM_], g_qlo[MT_ * DM_];
__device__ __half g_khi[MT_ * DM_], g_klo[MT_ * DM_];
__device__ __half g_v  [MT_ * DM_];
__device__ __half g_aohi[MT_ * DM_], g_aolo[MT_ * DM_];

// ---------------- helpers ---------------------------------------------------
__device__ __forceinline__ uint32_t smem_u32(const void* p) {
    uint32_t a;
    asm("{ .reg .u64 t; cvta.to.shared.u64 t, %1; cvt.u32.u64 %0, t; }" : "=r"(a) : "l"(p));
    return a;
}
__device__ __forceinline__ void cpa16(uint32_t dst, const void* src) {
    asm volatile("cp.async.cg.shared.global [%0], [%1], 16;" :: "r"(dst), "l"(src));
}
#define CP_COMMIT() asm volatile("cp.async.commit_group;" ::: "memory")
#define CP_WAIT0()  asm volatile("cp.async.wait_group 0;" ::: "memory")
#define CP_WAIT1()  asm volatile("cp.async.wait_group 1;" ::: "memory")

__device__ __forceinline__ void ldsm4(uint32_t* r, uint32_t addr) {
    asm volatile("ldmatrix.sync.aligned.m8n8.x4.shared.b16 {%0,%1,%2,%3}, [%4];"
        : "=r"(r[0]), "=r"(r[1]), "=r"(r[2]), "=r"(r[3]) : "r"(addr));
}
__device__ __forceinline__ void ldsm4t(uint32_t* r, uint32_t addr) {
    asm volatile("ldmatrix.sync.aligned.m8n8.x4.trans.shared.b16 {%0,%1,%2,%3}, [%4];"
        : "=r"(r[0]), "=r"(r[1]), "=r"(r[2]), "=r"(r[3]) : "r"(addr));
}
__device__ __forceinline__ void mma16816(float* c, const uint32_t* a, const uint32_t* b) {
    asm volatile("mma.sync.aligned.m16n8k16.row.col.f32.f16.f16.f32 "
        "{%0,%1,%2,%3}, {%4,%5,%6,%7}, {%8,%9}, {%0,%1,%2,%3};"
        : "+f"(c[0]), "+f"(c[1]), "+f"(c[2]), "+f"(c[3])
        : "r"(a[0]), "r"(a[1]), "r"(a[2]), "r"(a[3]), "r"(b[0]), "r"(b[1]));
}
__device__ __forceinline__ uint32_t hpack(__half a, __half b) {
    __half2 t; t.x = a; t.y = b;
    return *(uint32_t*)&t;
}
__device__ __forceinline__ uint32_t pack2h(float v0, float v1) {
    return hpack(__float2half_rn(v0), __float2half_rn(v1));
}
__device__ __forceinline__ void split2h(float v0, float v1, uint32_t& hi, uint32_t& lo) {
    __half h0 = __float2half_rn(v0), h1 = __float2half_rn(v1);
    __half l0 = __float2half_rn(v0 - __half2float(h0));
    __half l1 = __float2half_rn(v1 - __half2float(h1));
    hi = hpack(h0, h1); lo = hpack(l0, l1);
}
__device__ __forceinline__ uint32_t cvt_f16x2(float t0, float t1) {
    uint32_t r;
    asm("cvt.rn.f16x2.f32 %0, %1, %2;" : "=r"(r) : "f"(t1), "f"(t0));
    return r;
}
__device__ __forceinline__ uint32_t ex2_f16x2(uint32_t x) {
    uint32_t r;
    asm("ex2.approx.f16x2 %0, %1;" : "=r"(r) : "r"(x));
    return r;
}

// 144-B-stride tiles (attention) -> conflict-free ldmatrix
__device__ __forceinline__ uint32_t addrA(uint32_t base, int row, int col, int l) {
    return base + (uint32_t)((row + (l & 15)) * 144 + (col + (l >> 4) * 8) * 2);
}
__device__ __forceinline__ uint32_t addrB(uint32_t base, int row, int col, int l) {
    return base + (uint32_t)((row + ((l >> 4) & 1) * 8 + (l & 7)) * 144
                             + (col + ((l >> 3) & 1) * 8) * 2);
}
// 80-B-stride tiles (GEMM, BK=32)
__device__ __forceinline__ uint32_t addrA80(uint32_t base, int row, int col, int l) {
    return base + (uint32_t)((row + (l & 15)) * GROW + (col + (l >> 4) * 8) * 2);
}
__device__ __forceinline__ uint32_t addrB80(uint32_t base, int row, int col, int l) {
    return base + (uint32_t)((row + ((l >> 4) & 1) * 8 + (l & 7)) * GROW
                             + (col + ((l >> 3) & 1) * 8) * 2);
}

// ---------------------------------------------------------------------------
// fused conversions: blocks 0..8191 split current/hidden; 8192..9215 transpose
// + split/convert the weights. Both paths use 256-thread blocks.
// ---------------------------------------------------------------------------
__global__ void prep_all(const float* __restrict__ cur, const float* __restrict__ hid,
                         const float* __restrict__ Wq, const float* __restrict__ Wkv,
                         const float* __restrict__ Wo,
                         __half* __restrict__ curhi, __half* __restrict__ curlo,
                         __half* __restrict__ hidhi, __half* __restrict__ hidlo,
                         __half* __restrict__ wqThi, __half* __restrict__ wqTlo,
                         __half* __restrict__ wkvThi, __half* __restrict__ wkvTlo,
                         __half* __restrict__ woT, int n4)
{
    int blk = blockIdx.x;
    if (blk < 8192) {
        int i = blk * 256 + threadIdx.x;
        const float* x = (i < n4) ? cur : hid;
        __half* hh = (i < n4) ? curhi : hidhi;
        __half* ll = (i < n4) ? curlo : hidlo;
        int j = (i < n4) ? i : i - n4;
        float4 v = ((const float4*)x)[j];
        uint32_t a, b, c, d;
        split2h(v.x, v.y, a, b);
        split2h(v.z, v.w, c, d);
        ((uint32_t*)hh)[j * 2]     = a;
        ((uint32_t*)hh)[j * 2 + 1] = c;
        ((uint32_t*)ll)[j * 2]     = b;
        ((uint32_t*)ll)[j * 2 + 1] = d;
        return;
    }
    // weight transpose/convert
    __shared__ float tile[32][33];
    int bx = blk - 8192;
    int tx = threadIdx.x & 31, ty = threadIdx.x >> 5;   // 32 x 8
    const float* W; __half *Thi, *Tlo; int Nc, idx, do_split;
    if (bx < 256)      { W = Wq;  Thi = wqThi;  Tlo = wqTlo;  Nc = 512;  idx = bx;       do_split = 1; }
    else if (bx < 768) { W = Wkv; Thi = wkvThi; Tlo = wkvTlo; Nc = 1024; idx = bx - 256; do_split = 1; }
    else               { W = Wo;  Thi = woT;    Tlo = 0;      Nc = 512;  idx = bx - 768; do_split = 0; }
    int tn = Nc / 32;
    int n0 = (idx % tn) * 32, k0 = (idx / tn) * 32;
    for (int r = ty; r < 32; r += 8)
        tile[r][tx] = W[(size_t)(k0 + r) * Nc + n0 + tx];
    __syncthreads();
    for (int r = ty; r < 32; r += 8) {
        float x = tile[tx][r];
        __half h = __float2half_rn(x);
        size_t o = (size_t)(n0 + r) * 512 + k0 + tx;
        Thi[o] = h;
        if (do_split) Tlo[o] = __float2half_rn(x - __half2float(h));
    }
}

// ---------------------------------------------------------------------------
// GEMM tile: out[128x128] = (Ahi+Alo)[128x512] @ WT^T, 2/3 fp16 terms.
// BK=32, 2-stage cp.async pipeline, ONE barrier per chunk. 8 warps (2m x 4n).
// mode 0: fp32 out; mode 1: fp16 2-split out; mode 2: fp16 single out.
// ---------------------------------------------------------------------------
__device__ __forceinline__ void gemm_body(
    const __half* __restrict__ Ahi, const __half* __restrict__ Alo,
    const __half* __restrict__ WThi, const __half* __restrict__ WTlo,
    int m0, int n0w, int n0out, int terms, int mode,
    float* __restrict__ outf, __half* __restrict__ outhi, __half* __restrict__ outlo,
    char* smem)
{
    const uint32_t sb = smem_u32(smem);
    const int t = threadIdx.x, l = t & 31, w = t >> 5;
    const int wm = w >> 2, wn = w & 3;

    float c[4][4][4];
    #pragma unroll
    for (int i = 0; i < 4; i++)
        #pragma unroll
        for (int j = 0; j < 4; j++)
            #pragma unroll
            for (int e = 0; e < 4; e++) c[i][j][e] = 0.f;

    const int row = t >> 1, half = t & 1;
    const __half* gAh = Ahi  + (size_t)(m0 + row) * 512 + half * 16;
    const __half* gAl = Alo  + (size_t)(m0 + row) * 512 + half * 16;
    const __half* gWh = WThi + (size_t)(n0w + row) * 512 + half * 16;
    const __half* gWl = (terms == 3) ? WTlo + (size_t)(n0w + row) * 512 + half * 16 : gWh;
    const uint32_t db = (uint32_t)(row * GROW + half * 32);

    auto issue = [&](int c2, int st) {
        uint32_t so = sb + (uint32_t)st * GSTG + db;
        int ko = c2 * 32;
        cpa16(so + 0 * GBUF,      gAh + ko);
        cpa16(so + 0 * GBUF + 16, gAh + ko + 8);
        cpa16(so + 1 * GBUF,      gAl + ko);
        cpa16(so + 1 * GBUF + 16, gAl + ko + 8);
        cpa16(so + 2 * GBUF,      gWh + ko);
        cpa16(so + 2 * GBUF + 16, gWh + ko + 8);
        if (terms == 3) {
            cpa16(so + 3 * GBUF,      gWl + ko);
            cpa16(so + 3 * GBUF + 16, gWl + ko + 8);
        }
        CP_COMMIT();
    };

    issue(0, 0);

    for (int c2 = 0; c2 < 16; c2++) {
        CP_WAIT0();
        __syncthreads();
        if (c2 < 15) issue(c2 + 1, (c2 + 1) & 1);

        const uint32_t st = sb + (uint32_t)(c2 & 1) * GSTG;
        const uint32_t sAh = st, sAl = st + GBUF, sWh = st + 2 * GBUF, sWl = st + 3 * GBUF;

        #pragma unroll
        for (int kk = 0; kk < 2; kk++) {
            uint32_t ah[4][4], al[4][4];
            #pragma unroll
            for (int i = 0; i < 4; i++) {
                ldsm4(ah[i], addrA80(sAh, wm * 64 + i * 16, kk * 16, l));
                ldsm4(al[i], addrA80(sAl, wm * 64 + i * 16, kk * 16, l));
            }
            #pragma unroll
            for (int p = 0; p < 2; p++) {
                uint32_t bh[4], bl[4];
                ldsm4(bh, addrB80(sWh, wn * 32 + p * 16, kk * 16, l));
                if (terms == 3) ldsm4(bl, addrB80(sWl, wn * 32 + p * 16, kk * 16, l));
                #pragma unroll
                for (int i = 0; i < 4; i++) {
                    #pragma unroll
                    for (int q = 0; q < 2; q++) {
                        float* acc = c[i][p * 2 + q];
                        mma16816(acc, ah[i], bh + q * 2);
                        mma16816(acc, al[i], bh + q * 2);
                        if (terms == 3) mma16816(acc, ah[i], bl + q * 2);
                    }
                }
            }
        }
    }

    #pragma unroll
    for (int i = 0; i < 4; i++) {
        #pragma unroll
        for (int jn = 0; jn < 4; jn++) {
            int r0 = m0 + wm * 64 + i * 16 + (l >> 2);
            int cc = n0out + wn * 32 + jn * 8 + (l & 3) * 2;
            float* acc = c[i][jn];
            if (mode == 0) {
                *(float2*)(outf + (size_t)r0 * 512 + cc)       = make_float2(acc[0], acc[1]);
                *(float2*)(outf + (size_t)(r0 + 8) * 512 + cc) = make_float2(acc[2], acc[3]);
            } else if (mode == 1) {
                uint32_t h0, l0, h1, l1;
                split2h(acc[0], acc[1], h0, l0);
                split2h(acc[2], acc[3], h1, l1);
                *(uint32_t*)(outhi + (size_t)r0 * 512 + cc)       = h0;
                *(uint32_t*)(outlo + (size_t)r0 * 512 + cc)       = l0;
                *(uint32_t*)(outhi + (size_t)(r0 + 8) * 512 + cc) = h1;
                *(uint32_t*)(outlo + (size_t)(r0 + 8) * 512 + cc) = l1;
            } else {
                *(uint32_t*)(outhi + (size_t)r0 * 512 + cc)       = pack2h(acc[0], acc[1]);
                *(uint32_t*)(outhi + (size_t)(r0 + 8) * 512 + cc) = pack2h(acc[2], acc[3]);
            }
        }
    }
}

// grid (12, 64): bx 0-3 Q (3t, split), 4-7 K (3t, split), 8-11 V (2t, single)
__global__ __launch_bounds__(256, 2)
void proj_qkv(const __half* __restrict__ curhi, const __half* __restrict__ curlo,
              const __half* __restrict__ hidhi, const __half* __restrict__ hidlo,
              const __half* __restrict__ wqThi, const __half* __restrict__ wqTlo,
              const __half* __restrict__ wkvThi, const __half* __restrict__ wkvTlo,
              __half* __restrict__ qhi, __half* __restrict__ qlo,
              __half* __restrict__ khi, __half* __restrict__ klo,
              __half* __restrict__ vv)
{
    extern __shared__ __align__(1024) char smem[];
    int bx = blockIdx.x, m0 = blockIdx.y * 128;
    if (bx < 4)
        gemm_body(curhi, curlo, wqThi, wqTlo, m0, bx * 128, bx * 128, 3, 1,
                  nullptr, qhi, qlo, smem);
    else if (bx < 8)
        gemm_body(hidhi, hidlo, wkvThi, wkvTlo, m0, (bx - 4) * 128, (bx - 4) * 128,
                  3, 1, nullptr, khi, klo, smem);
    else
        gemm_body(hidhi, hidlo, wkvThi, wkvTlo, m0, 512 + (bx - 8) * 128,
                  (bx - 8) * 128, 2, 2, nullptr, vv, nullptr, smem);
}

__global__ __launch_bounds__(256, 2)
void proj_out(const __half* __restrict__ aohi, const __half* __restrict__ aolo,
              const __half* __restrict__ woT, float* __restrict__ out)
{
    extern __shared__ __align__(1024) char smem[];
    gemm_body(aohi, aolo, woT, nullptr, blockIdx.y * 128, blockIdx.x * 128,
              blockIdx.x * 128, 2, 0, out, nullptr, nullptr, smem);
}

// ---------------------------------------------------------------------------
// Attention, online-max softmax w/ lazy rescale (NO 1/sqrt(d) scale).
// Block = (b,h) x 128 q-rows, 8 warps x 16 q-rows, two CTAs per SM.
// THREE-stage (Khi,Klo,V) pipeline, wait_group(1), ONE barrier per k-tile.
// S: Q 2-split x K 2-split (3 terms). P: ex2.approx.f16x2 packed fp16.
// lsum via ones-column mma. PV: 1 term.
// ---------------------------------------------------------------------------
__global__ __launch_bounds__(256, 2)
void attn_mma(const __half* __restrict__ Qhi, const __half* __restrict__ Qlo,
              const __half* __restrict__ Khi, const __half* __restrict__ Klo,
              const __half* __restrict__ Vv,
              __half* __restrict__ AOhi, __half* __restrict__ AOlo)
{
    extern __shared__ __align__(1024) char smem[];
    const uint32_t sb = smem_u32(smem);
    const uint32_t sQh = sb, sQl = sb + GB;
    const uint32_t kvbase = sb + 2 * GB;      // 3 stages x (Khi, Klo, V)

    const int t = threadIdx.x, l = t & 31, w = t >> 5;
    const int b = blockIdx.x >> 3, h = blockIdx.x & 7;
    const int q0 = blockIdx.y * 128;
    const float LOG2E = 1.4426950408889634f;

    uint32_t bones[2];
    bones[0] = bones[1] = ((l >> 2) == 0) ? 0x3C003C00u : 0u;

    // stage resident Q tile
    {
        const int row = t >> 1, half = t & 1;
        const __half* gh = Qhi + (size_t)(b * N_ + q0 + row) * 512 + h * 64 + half * 32;
        const __half* gl = Qlo + (size_t)(b * N_ + q0 + row) * 512 + h * 64 + half * 32;
        char* dh = smem +      row * 144 + half * 64;
        char* dl = smem + GB + row * 144 + half * 64;
        #pragma unroll
        for (int v = 0; v < 4; v++) {
            ((uint4*)dh)[v] = ((const uint4*)gh)[v];
            ((uint4*)dl)[v] = ((const uint4*)gl)[v];
        }
    }

    // KV staging: 384 half-row tasks over 256 threads
    auto issue_kv = [&](int kt, int st) {
        uint32_t stb = kvbase + (uint32_t)st * KVSTG;
        for (int i = t; i < 384; i += 256) {
            int buf = i >> 7, rr = (i & 127) >> 1, hf = i & 1;
            const __half* base = (buf == 0) ? Khi : (buf == 1) ? Klo : Vv;
            const __half* src = base + (size_t)(b * N_ + kt * 64 + rr) * 512
                                + h * 64 + hf * 32;
            uint32_t d = stb + (uint32_t)(buf * KVB + rr * 144 + hf * 64);
            #pragma unroll
            for (int v = 0; v < 4; v++)
                cpa16(d + v * 16, src + v * 8);
        }
        CP_COMMIT();
    };

    issue_kv(0, 0);
    issue_kv(1, 1);

    float o[8][4];
    #pragma unroll
    for (int i = 0; i < 8; i++)
        #pragma unroll
        for (int e = 0; e < 4; e++) o[i][e] = 0.f;
    float lsA[4] = {0.f, 0.f, 0.f, 0.f};
    float m0r = -1e30f, m1r = -1e30f;
    float m0s = 0.f, m1s = 0.f;

    for (int kt = 0; kt < 16; kt++) {
        CP_WAIT1();          // tile kt arrived (kt+1 may still be in flight)
        __syncthreads();     // all warps done with stage (kt+2)%3's old tile
        if (kt < 14) issue_kv(kt + 2, (kt + 2) % 3);

        const uint32_t stb = kvbase + (uint32_t)(kt % 3) * KVSTG;
        const uint32_t sKh = stb, sKl = stb + KVB, sV = stb + 2 * KVB;

        // ---- S = Q K^T (3 terms) ----
        float s[8][4];
        #pragma unroll
        for (int i = 0; i < 8; i++)
            #pragma unroll
            for (int e = 0; e < 4; e++) s[i][e] = 0.f;

        #pragma unroll
        for (int kk = 0; kk < 4; kk++) {
            uint32_t qh[4], ql[4];
            ldsm4(qh, addrA(sQh, w * 16, kk * 16, l));
            ldsm4(ql, addrA(sQl, w * 16, kk * 16, l));
            #pragma unroll
            for (int p = 0; p < 4; p++) {
                uint32_t bh[4], bl[4];
                ldsm4(bh, addrB(sKh, p * 16, kk * 16, l));
                ldsm4(bl, addrB(sKl, p * 16, kk * 16, l));
                #pragma unroll
                for (int q = 0; q < 2; q++) {
                    float* acc = s[p * 2 + q];
                    mma16816(acc, qh, bh + q * 2);
                    mma16816(acc, ql, bh + q * 2);
                    mma16816(acc, qh, bl + q * 2);
                }
            }
        }

        // ---- online max; rescale only if max advanced (warp-uniform) ----
        float rm0 = -1e30f, rm1 = -1e30f;
        #pragma unroll
        for (int jn = 0; jn < 8; jn++) {
            rm0 = fmaxf(rm0, fmaxf(s[jn][0], s[jn][1]));
            rm1 = fmaxf(rm1, fmaxf(s[jn][2], s[jn][3]));
        }
        rm0 = fmaxf(rm0, __shfl_xor_sync(0xffffffffu, rm0, 1));
        rm0 = fmaxf(rm0, __shfl_xor_sync(0xffffffffu, rm0, 2));
        rm1 = fmaxf(rm1, __shfl_xor_sync(0xffffffffu, rm1, 1));
        rm1 = fmaxf(rm1, __shfl_xor_sync(0xffffffffu, rm1, 2));
        if (rm0 > m0r) {
            float sc0 = __expf(m0r - rm0);
            m0r = rm0; m0s = rm0 * LOG2E;
            lsA[0] *= sc0; lsA[1] *= sc0;
            #pragma unroll
            for (int i = 0; i < 8; i++) { o[i][0] *= sc0; o[i][1] *= sc0; }
        }
        if (rm1 > m1r) {
            float sc1 = __expf(m1r - rm1);
            m1r = rm1; m1s = rm1 * LOG2E;
            lsA[2] *= sc1; lsA[3] *= sc1;
            #pragma unroll
            for (int i = 0; i < 8; i++) { o[i][2] *= sc1; o[i][3] *= sc1; }
        }

        // ---- P = exp2(s*log2e - m*log2e) via ex2.approx.f16x2 ----
        uint32_t pa[4][4];
        #pragma unroll
        for (int jn = 0; jn < 8; jn++) {
            float t0 = fmaf(s[jn][0], LOG2E, -m0s);
            float t1 = fmaf(s[jn][1], LOG2E, -m0s);
            float t2 = fmaf(s[jn][2], LOG2E, -m1s);
            float t3 = fmaf(s[jn][3], LOG2E, -m1s);
            int kj = jn >> 1, base = (jn & 1) * 2;
            pa[kj][base + 0] = ex2_f16x2(cvt_f16x2(t0, t1));
            pa[kj][base + 1] = ex2_f16x2(cvt_f16x2(t2, t3));
        }

        // ---- lsum += row-sums of P (ones column) ----
        #pragma unroll
        for (int kj = 0; kj < 4; kj++)
            mma16816(lsA, pa[kj], bones);

        // ---- O += P V (1 term) ----
        #pragma unroll
        for (int kj = 0; kj < 4; kj++) {
            #pragma unroll
            for (int pd = 0; pd < 4; pd++) {
                uint32_t bv[4];
                uint32_t va = (uint32_t)((kj * 16 + ((l >> 3) & 1) * 8 + (l & 7)) * 144
                                         + (pd * 16 + ((l >> 4) & 1) * 8) * 2);
                ldsm4t(bv, sV + va);
                #pragma unroll
                for (int q = 0; q < 2; q++)
                    mma16816(o[pd * 2 + q], pa[kj], bv + q * 2);
            }
        }
    }

    float ls0 = __shfl_sync(0xffffffffu, lsA[0], l & 28);
    float ls1 = __shfl_sync(0xffffffffu, lsA[2], l & 28);
    float inv0 = 1.f / ls0, inv1 = 1.f / ls1;

    const int rowg = b * N_ + q0 + w * 16 + (l >> 2);
    #pragma unroll
    for (int dn = 0; dn < 8; dn++) {
        int cc = h * 64 + dn * 8 + (l & 3) * 2;
        uint32_t h0, l0, h1, l1;
        split2h(o[dn][0] * inv0, o[dn][1] * inv0, h0, l0);
        split2h(o[dn][2] * inv1, o[dn][3] * inv1, h1, l1);
        *(uint32_t*)(AOhi + (size_t)rowg * 512 + cc)       = h0;
        *(uint32_t*)(AOlo + (size_t)rowg * 512 + cc)       = l0;
        *(uint32_t*)(AOhi + (size_t)(rowg + 8) * 512 + cc) = h1;
        *(uint32_t*)(AOlo + (size_t)(rowg + 8) * 512 + cc) = l1;
    }
}

// ---------------------------------------------------------------------------
extern "C" void kernel_launch(void* const* d_in, const int* in_sizes, int n_in,
                              void* d_out, int out_size)
{
    (void)in_sizes; (void)n_in; (void)out_size;
    const float* current = (const float*)d_in[0];
    const float* hidden  = (const float*)d_in[1];
    const float* Wq      = (const float*)d_in[2];
    const float* Wkv     = (const float*)d_in[3];
    const float* Wo      = (const float*)d_in[4];
    float* out           = (float*)d_out;

    __half *curhi, *curlo, *hidhi, *hidlo;
    __half *wqThi, *wqTlo, *wkvThi, *wkvTlo, *woT;
    __half *qhi, *qlo, *khi, *klo, *vv, *aohi, *aolo;
    cudaGetSymbolAddress((void**)&curhi, g_curhi); cudaGetSymbolAddress((void**)&curlo, g_curlo);
    cudaGetSymbolAddress((void**)&hidhi, g_hidhi); cudaGetSymbolAddress((void**)&hidlo, g_hidlo);
    cudaGetSymbolAddress((void**)&wqThi, g_wqThi); cudaGetSymbolAddress((void**)&wqTlo, g_wqTlo);
    cudaGetSymbolAddress((void**)&wkvThi, g_wkvThi); cudaGetSymbolAddress((void**)&wkvTlo, g_wkvTlo);
    cudaGetSymbolAddress((void**)&woT, g_woT);
    cudaGetSymbolAddress((void**)&qhi, g_qhi);   cudaGetSymbolAddress((void**)&qlo, g_qlo);
    cudaGetSymbolAddress((void**)&khi, g_khi);   cudaGetSymbolAddress((void**)&klo, g_klo);
    cudaGetSymbolAddress((void**)&vv,  g_v);
    cudaGetSymbolAddress((void**)&aohi, g_aohi); cudaGetSymbolAddress((void**)&aolo, g_aolo);

    const int gemm_smem = 2 * GSTG;                  // 81920
    const int attn_smem = 2 * GB + 3 * KVSTG;        // 119808
    cudaFuncSetAttribute(proj_qkv, cudaFuncAttributeMaxDynamicSharedMemorySize, gemm_smem);
    cudaFuncSetAttribute(proj_out, cudaFuncAttributeMaxDynamicSharedMemorySize, gemm_smem);
    cudaFuncSetAttribute(attn_mma, cudaFuncAttributeMaxDynamicSharedMemorySize, attn_smem);

    const int n4 = MT_ * DM_ / 4;
    prep_all<<<8192 + 1024, 256>>>(current, hidden, Wq, Wkv, Wo,
                                   curhi, curlo, hidhi, hidlo,
                                   wqThi, wqTlo, wkvThi, wkvTlo, woT, n4);

    proj_qkv<<<dim3(12, 64), 256, gemm_smem>>>(curhi, curlo, hidhi, hidlo,
                                               wqThi, wqTlo, wkvThi, wkvTlo,
                                               qhi, qlo, khi, klo, vv);
    attn_mma<<<dim3(B_ * H_, N_ / 128), 256, attn_smem>>>(qhi, qlo, khi, klo, vv,
                                                          aohi, aolo);
    proj_out<<<dim3(4, 64), 256, gemm_smem>>>(aohi, aolo, woT, out);
}

// round 15
// speedup vs baseline: 1.0677x; 1.0677x over previous
#include <cuda_runtime.h>
#include <cuda_fp16.h>
#include <cstdint>
#include <math.h>

#define B_   8
#define N_   1024
#define DM_  512
#define H_   8
#define MT_  (B_ * N_)      // 8192
#define GB   18432          // 128 rows x 144 B (Q tiles in attention)

// GEMM pipeline geometry: BK=32, rows of 80 B, 4 buffers, 2 stages
#define GROW 80
#define GBUF 10240          // 128 * 80
#define GSTG 40960          // 4 * GBUF
// Attention KV stage: 3 buffers (Khi, Klo, V) x (64 rows x 144 B), 2 stages
#define KVB  9216
#define KVSTG (3 * KVB)     // 27648

// ---------------- fp16 scratch (__device__ globals; no allocs) -------------
__device__ __half g_curhi[MT_ * DM_], g_curlo[MT_ * DM_];
__device__ __half g_hidhi[MT_ * DM_], g_hidlo[MT_ * DM_];
__device__ __half g_wqThi [DM_ * DM_],     g_wqTlo [DM_ * DM_];
__device__ __half g_wkvThi[2 * DM_ * DM_], g_wkvTlo[2 * DM_ * DM_];
__device__ __half g_woT   [DM_ * DM_];
__device__ __half g_qhi[MT_ * DM_], g_qlo[MT_ * DM_];
__device__ __half g_khi[MT_ * DM_], g_klo[MT_ * DM_];
__device__ __half g_v  [MT_ * DM_];
__device__ __half g_aohi[MT_ * DM_], g_aolo[MT_ * DM_];

// ---------------- helpers ---------------------------------------------------
__device__ __forceinline__ uint32_t smem_u32(const void* p) {
    uint32_t a;
    asm("{ .reg .u64 t; cvta.to.shared.u64 t, %1; cvt.u32.u64 %0, t; }" : "=r"(a) : "l"(p));
    return a;
}
__device__ __forceinline__ void cpa16(uint32_t dst, const void* src) {
    asm volatile("cp.async.cg.shared.global [%0], [%1], 16;" :: "r"(dst), "l"(src));
}
#define CP_COMMIT() asm volatile("cp.async.commit_group;" ::: "memory")
#define CP_WAIT0()  asm volatile("cp.async.wait_group 0;" ::: "memory")

__device__ __forceinline__ void ldsm4(uint32_t* r, uint32_t addr) {
    asm volatile("ldmatrix.sync.aligned.m8n8.x4.shared.b16 {%0,%1,%2,%3}, [%4];"
        : "=r"(r[0]), "=r"(r[1]), "=r"(r[2]), "=r"(r[3]) : "r"(addr));
}
__device__ __forceinline__ void ldsm4t(uint32_t* r, uint32_t addr) {
    asm volatile("ldmatrix.sync.aligned.m8n8.x4.trans.shared.b16 {%0,%1,%2,%3}, [%4];"
        : "=r"(r[0]), "=r"(r[1]), "=r"(r[2]), "=r"(r[3]) : "r"(addr));
}
__device__ __forceinline__ void mma16816(float* c, const uint32_t* a, const uint32_t* b) {
    asm volatile("mma.sync.aligned.m16n8k16.row.col.f32.f16.f16.f32 "
        "{%0,%1,%2,%3}, {%4,%5,%6,%7}, {%8,%9}, {%0,%1,%2,%3};"
        : "+f"(c[0]), "+f"(c[1]), "+f"(c[2]), "+f"(c[3])
        : "r"(a[0]), "r"(a[1]), "r"(a[2]), "r"(a[3]), "r"(b[0]), "r"(b[1]));
}
__device__ __forceinline__ uint32_t hpack(__half a, __half b) {
    __half2 t; t.x = a; t.y = b;
    return *(uint32_t*)&t;
}
__device__ __forceinline__ uint32_t pack2h(float v0, float v1) {
    return hpack(__float2half_rn(v0), __float2half_rn(v1));
}
__device__ __forceinline__ void split2h(float v0, float v1, uint32_t& hi, uint32_t& lo) {
    __half h0 = __float2half_rn(v0), h1 = __float2half_rn(v1);
    __half l0 = __float2half_rn(v0 - __half2float(h0));
    __half l1 = __float2half_rn(v1 - __half2float(h1));
    hi = hpack(h0, h1); lo = hpack(l0, l1);
}
__device__ __forceinline__ uint32_t cvt_f16x2(float t0, float t1) {
    uint32_t r;
    asm("cvt.rn.f16x2.f32 %0, %1, %2;" : "=r"(r) : "f"(t1), "f"(t0));
    return r;
}
__device__ __forceinline__ uint32_t ex2_f16x2(uint32_t x) {
    uint32_t r;
    asm("ex2.approx.f16x2 %0, %1;" : "=r"(r) : "r"(x));
    return r;
}

// 144-B-stride tiles (attention) -> conflict-free ldmatrix
__device__ __forceinline__ uint32_t addrA(uint32_t base, int row, int col, int l) {
    return base + (uint32_t)((row + (l & 15)) * 144 + (col + (l >> 4) * 8) * 2);
}
__device__ __forceinline__ uint32_t addrB(uint32_t base, int row, int col, int l) {
    return base + (uint32_t)((row + ((l >> 4) & 1) * 8 + (l & 7)) * 144
                             + (col + ((l >> 3) & 1) * 8) * 2);
}
// 80-B-stride tiles (GEMM, BK=32)
__device__ __forceinline__ uint32_t addrA80(uint32_t base, int row, int col, int l) {
    return base + (uint32_t)((row + (l & 15)) * GROW + (col + (l >> 4) * 8) * 2);
}
__device__ __forceinline__ uint32_t addrB80(uint32_t base, int row, int col, int l) {
    return base + (uint32_t)((row + ((l >> 4) & 1) * 8 + (l & 7)) * GROW
                             + (col + ((l >> 3) & 1) * 8) * 2);
}

// ---------------------------------------------------------------------------
// fused conversions: blocks 0..8191 split current/hidden; 8192..9215 transpose
// + split/convert the weights. Both paths use 256-thread blocks.
// ---------------------------------------------------------------------------
__global__ void prep_all(const float* __restrict__ cur, const float* __restrict__ hid,
                         const float* __restrict__ Wq, const float* __restrict__ Wkv,
                         const float* __restrict__ Wo,
                         __half* __restrict__ curhi, __half* __restrict__ curlo,
                         __half* __restrict__ hidhi, __half* __restrict__ hidlo,
                         __half* __restrict__ wqThi, __half* __restrict__ wqTlo,
                         __half* __restrict__ wkvThi, __half* __restrict__ wkvTlo,
                         __half* __restrict__ woT, int n4)
{
    int blk = blockIdx.x;
    if (blk < 8192) {
        int i = blk * 256 + threadIdx.x;
        const float* x = (i < n4) ? cur : hid;
        __half* hh = (i < n4) ? curhi : hidhi;
        __half* ll = (i < n4) ? curlo : hidlo;
        int j = (i < n4) ? i : i - n4;
        float4 v = ((const float4*)x)[j];
        uint32_t a, b, c, d;
        split2h(v.x, v.y, a, b);
        split2h(v.z, v.w, c, d);
        ((uint32_t*)hh)[j * 2]     = a;
        ((uint32_t*)hh)[j * 2 + 1] = c;
        ((uint32_t*)ll)[j * 2]     = b;
        ((uint32_t*)ll)[j * 2 + 1] = d;
        return;
    }
    // weight transpose/convert
    __shared__ float tile[32][33];
    int bx = blk - 8192;
    int tx = threadIdx.x & 31, ty = threadIdx.x >> 5;   // 32 x 8
    const float* W; __half *Thi, *Tlo; int Nc, idx, do_split;
    if (bx < 256)      { W = Wq;  Thi = wqThi;  Tlo = wqTlo;  Nc = 512;  idx = bx;       do_split = 1; }
    else if (bx < 768) { W = Wkv; Thi = wkvThi; Tlo = wkvTlo; Nc = 1024; idx = bx - 256; do_split = 1; }
    else               { W = Wo;  Thi = woT;    Tlo = 0;      Nc = 512;  idx = bx - 768; do_split = 0; }
    int tn = Nc / 32;
    int n0 = (idx % tn) * 32, k0 = (idx / tn) * 32;
    for (int r = ty; r < 32; r += 8)
        tile[r][tx] = W[(size_t)(k0 + r) * Nc + n0 + tx];
    __syncthreads();
    for (int r = ty; r < 32; r += 8) {
        float x = tile[tx][r];
        __half h = __float2half_rn(x);
        size_t o = (size_t)(n0 + r) * 512 + k0 + tx;
        Thi[o] = h;
        if (do_split) Tlo[o] = __float2half_rn(x - __half2float(h));
    }
}

// ---------------------------------------------------------------------------
// GEMM tile: out[128x128] = (Ahi+Alo)[128x512] @ WT^T, 2/3 fp16 terms.
// BK=32, 2-stage cp.async pipeline, ONE barrier per chunk. 8 warps (2m x 4n).
// mode 0: fp32 out; mode 1: fp16 2-split out; mode 2: fp16 single out.
// ---------------------------------------------------------------------------
__device__ __forceinline__ void gemm_body(
    const __half* __restrict__ Ahi, const __half* __restrict__ Alo,
    const __half* __restrict__ WThi, const __half* __restrict__ WTlo,
    int m0, int n0w, int n0out, int terms, int mode,
    float* __restrict__ outf, __half* __restrict__ outhi, __half* __restrict__ outlo,
    char* smem)
{
    const uint32_t sb = smem_u32(smem);
    const int t = threadIdx.x, l = t & 31, w = t >> 5;
    const int wm = w >> 2, wn = w & 3;

    float c[4][4][4];
    #pragma unroll
    for (int i = 0; i < 4; i++)
        #pragma unroll
        for (int j = 0; j < 4; j++)
            #pragma unroll
            for (int e = 0; e < 4; e++) c[i][j][e] = 0.f;

    const int row = t >> 1, half = t & 1;
    const __half* gAh = Ahi  + (size_t)(m0 + row) * 512 + half * 16;
    const __half* gAl = Alo  + (size_t)(m0 + row) * 512 + half * 16;
    const __half* gWh = WThi + (size_t)(n0w + row) * 512 + half * 16;
    const __half* gWl = (terms == 3) ? WTlo + (size_t)(n0w + row) * 512 + half * 16 : gWh;
    const uint32_t db = (uint32_t)(row * GROW + half * 32);

    auto issue = [&](int c2, int st) {
        uint32_t so = sb + (uint32_t)st * GSTG + db;
        int ko = c2 * 32;
        cpa16(so + 0 * GBUF,      gAh + ko);
        cpa16(so + 0 * GBUF + 16, gAh + ko + 8);
        cpa16(so + 1 * GBUF,      gAl + ko);
        cpa16(so + 1 * GBUF + 16, gAl + ko + 8);
        cpa16(so + 2 * GBUF,      gWh + ko);
        cpa16(so + 2 * GBUF + 16, gWh + ko + 8);
        if (terms == 3) {
            cpa16(so + 3 * GBUF,      gWl + ko);
            cpa16(so + 3 * GBUF + 16, gWl + ko + 8);
        }
        CP_COMMIT();
    };

    issue(0, 0);

    for (int c2 = 0; c2 < 16; c2++) {
        CP_WAIT0();
        __syncthreads();
        if (c2 < 15) issue(c2 + 1, (c2 + 1) & 1);

        const uint32_t st = sb + (uint32_t)(c2 & 1) * GSTG;
        const uint32_t sAh = st, sAl = st + GBUF, sWh = st + 2 * GBUF, sWl = st + 3 * GBUF;

        #pragma unroll
        for (int kk = 0; kk < 2; kk++) {
            uint32_t ah[4][4], al[4][4];
            #pragma unroll
            for (int i = 0; i < 4; i++) {
                ldsm4(ah[i], addrA80(sAh, wm * 64 + i * 16, kk * 16, l));
                ldsm4(al[i], addrA80(sAl, wm * 64 + i * 16, kk * 16, l));
            }
            #pragma unroll
            for (int p = 0; p < 2; p++) {
                uint32_t bh[4], bl[4];
                ldsm4(bh, addrB80(sWh, wn * 32 + p * 16, kk * 16, l));
                if (terms == 3) ldsm4(bl, addrB80(sWl, wn * 32 + p * 16, kk * 16, l));
                #pragma unroll
                for (int i = 0; i < 4; i++) {
                    #pragma unroll
                    for (int q = 0; q < 2; q++) {
                        float* acc = c[i][p * 2 + q];
                        mma16816(acc, ah[i], bh + q * 2);
                        mma16816(acc, al[i], bh + q * 2);
                        if (terms == 3) mma16816(acc, ah[i], bl + q * 2);
                    }
                }
            }
        }
    }

    #pragma unroll
    for (int i = 0; i < 4; i++) {
        #pragma unroll
        for (int jn = 0; jn < 4; jn++) {
            int r0 = m0 + wm * 64 + i * 16 + (l >> 2);
            int cc = n0out + wn * 32 + jn * 8 + (l & 3) * 2;
            float* acc = c[i][jn];
            if (mode == 0) {
                *(float2*)(outf + (size_t)r0 * 512 + cc)       = make_float2(acc[0], acc[1]);
                *(float2*)(outf + (size_t)(r0 + 8) * 512 + cc) = make_float2(acc[2], acc[3]);
            } else if (mode == 1) {
                uint32_t h0, l0, h1, l1;
                split2h(acc[0], acc[1], h0, l0);
                split2h(acc[2], acc[3], h1, l1);
                *(uint32_t*)(outhi + (size_t)r0 * 512 + cc)       = h0;
                *(uint32_t*)(outlo + (size_t)r0 * 512 + cc)       = l0;
                *(uint32_t*)(outhi + (size_t)(r0 + 8) * 512 + cc) = h1;
                *(uint32_t*)(outlo + (size_t)(r0 + 8) * 512 + cc) = l1;
            } else {
                *(uint32_t*)(outhi + (size_t)r0 * 512 + cc)       = pack2h(acc[0], acc[1]);
                *(uint32_t*)(outhi + (size_t)(r0 + 8) * 512 + cc) = pack2h(acc[2], acc[3]);
            }
        }
    }
}

// grid (12, 64): bx 0-3 Q (3t, split), 4-7 K (3t, split), 8-11 V (2t, single)
__global__ __launch_bounds__(256, 2)
void proj_qkv(const __half* __restrict__ curhi, const __half* __restrict__ curlo,
              const __half* __restrict__ hidhi, const __half* __restrict__ hidlo,
              const __half* __restrict__ wqThi, const __half* __restrict__ wqTlo,
              const __half* __restrict__ wkvThi, const __half* __restrict__ wkvTlo,
              __half* __restrict__ qhi, __half* __restrict__ qlo,
              __half* __restrict__ khi, __half* __restrict__ klo,
              __half* __restrict__ vv)
{
    extern __shared__ __align__(1024) char smem[];
    int bx = blockIdx.x, m0 = blockIdx.y * 128;
    if (bx < 4)
        gemm_body(curhi, curlo, wqThi, wqTlo, m0, bx * 128, bx * 128, 3, 1,
                  nullptr, qhi, qlo, smem);
    else if (bx < 8)
        gemm_body(hidhi, hidlo, wkvThi, wkvTlo, m0, (bx - 4) * 128, (bx - 4) * 128,
                  3, 1, nullptr, khi, klo, smem);
    else
        gemm_body(hidhi, hidlo, wkvThi, wkvTlo, m0, 512 + (bx - 8) * 128,
                  (bx - 8) * 128, 2, 2, nullptr, vv, nullptr, smem);
}

__global__ __launch_bounds__(256, 2)
void proj_out(const __half* __restrict__ aohi, const __half* __restrict__ aolo,
              const __half* __restrict__ woT, float* __restrict__ out)
{
    extern __shared__ __align__(1024) char smem[];
    gemm_body(aohi, aolo, woT, nullptr, blockIdx.y * 128, blockIdx.x * 128,
              blockIdx.x * 128, 2, 0, out, nullptr, nullptr, smem);
}

// ---------------------------------------------------------------------------
// Attention, online-max softmax w/ lazy rescale (NO 1/sqrt(d) scale).
// Block = (b,h) x 128 q-rows, 8 warps x 16 q-rows, two CTAs per SM (92,160 B
// smem/CTA -- MUST stay <= 114 KB for occ 2).
// 2-stage (Khi,Klo,V) pipeline, ONE barrier per k-tile.
// S: Q 2-split x K 2-split (3 terms). P: ex2.approx.f16x2 packed fp16.
// lsum via ones-column mma. PV: 1 term.
// ---------------------------------------------------------------------------
__global__ __launch_bounds__(256, 2)
void attn_mma(const __half* __restrict__ Qhi, const __half* __restrict__ Qlo,
              const __half* __restrict__ Khi, const __half* __restrict__ Klo,
              const __half* __restrict__ Vv,
              __half* __restrict__ AOhi, __half* __restrict__ AOlo)
{
    extern __shared__ __align__(1024) char smem[];
    const uint32_t sb = smem_u32(smem);
    const uint32_t sQh = sb, sQl = sb + GB;
    const uint32_t kvbase = sb + 2 * GB;      // 2 stages x (Khi, Klo, V)

    const int t = threadIdx.x, l = t & 31, w = t >> 5;
    const int b = blockIdx.x >> 3, h = blockIdx.x & 7;
    const int q0 = blockIdx.y * 128;
    const float LOG2E = 1.4426950408889634f;

    uint32_t bones[2];
    bones[0] = bones[1] = ((l >> 2) == 0) ? 0x3C003C00u : 0u;

    // stage resident Q tile
    {
        const int row = t >> 1, half = t & 1;
        const __half* gh = Qhi + (size_t)(b * N_ + q0 + row) * 512 + h * 64 + half * 32;
        const __half* gl = Qlo + (size_t)(b * N_ + q0 + row) * 512 + h * 64 + half * 32;
        char* dh = smem +      row * 144 + half * 64;
        char* dl = smem + GB + row * 144 + half * 64;
        #pragma unroll
        for (int v = 0; v < 4; v++) {
            ((uint4*)dh)[v] = ((const uint4*)gh)[v];
            ((uint4*)dl)[v] = ((const uint4*)gl)[v];
        }
    }

    // KV staging: 384 half-row tasks over 256 threads
    auto issue_kv = [&](int kt, int st) {
        uint32_t stb = kvbase + (uint32_t)st * KVSTG;
        for (int i = t; i < 384; i += 256) {
            int buf = i >> 7, rr = (i & 127) >> 1, hf = i & 1;
            const __half* base = (buf == 0) ? Khi : (buf == 1) ? Klo : Vv;
            const __half* src = base + (size_t)(b * N_ + kt * 64 + rr) * 512
                                + h * 64 + hf * 32;
            uint32_t d = stb + (uint32_t)(buf * KVB + rr * 144 + hf * 64);
            #pragma unroll
            for (int v = 0; v < 4; v++)
                cpa16(d + v * 16, src + v * 8);
        }
        CP_COMMIT();
    };

    issue_kv(0, 0);

    float o[8][4];
    #pragma unroll
    for (int i = 0; i < 8; i++)
        #pragma unroll
        for (int e = 0; e < 4; e++) o[i][e] = 0.f;
    float lsA[4] = {0.f, 0.f, 0.f, 0.f};
    float m0r = -1e30f, m1r = -1e30f;
    float m0s = 0.f, m1s = 0.f;

    for (int kt = 0; kt < 16; kt++) {
        CP_WAIT0();
        __syncthreads();
        if (kt < 15) issue_kv(kt + 1, (kt + 1) & 1);

        const uint32_t stb = kvbase + (uint32_t)(kt & 1) * KVSTG;
        const uint32_t sKh = stb, sKl = stb + KVB, sV = stb + 2 * KVB;

        // ---- S = Q K^T (3 terms) ----
        float s[8][4];
        #pragma unroll
        for (int i = 0; i < 8; i++)
            #pragma unroll
            for (int e = 0; e < 4; e++) s[i][e] = 0.f;

        #pragma unroll
        for (int kk = 0; kk < 4; kk++) {
            uint32_t qh[4], ql[4];
            ldsm4(qh, addrA(sQh, w * 16, kk * 16, l));
            ldsm4(ql, addrA(sQl, w * 16, kk * 16, l));
            #pragma unroll
            for (int p = 0; p < 4; p++) {
                uint32_t bh[4], bl[4];
                ldsm4(bh, addrB(sKh, p * 16, kk * 16, l));
                ldsm4(bl, addrB(sKl, p * 16, kk * 16, l));
                #pragma unroll
                for (int q = 0; q < 2; q++) {
                    float* acc = s[p * 2 + q];
                    mma16816(acc, qh, bh + q * 2);
                    mma16816(acc, ql, bh + q * 2);
                    mma16816(acc, qh, bl + q * 2);
                }
            }
        }

        // ---- online max; rescale only if max advanced (warp-uniform) ----
        float rm0 = -1e30f, rm1 = -1e30f;
        #pragma unroll
        for (int jn = 0; jn < 8; jn++) {
            rm0 = fmaxf(rm0, fmaxf(s[jn][0], s[jn][1]));
            rm1 = fmaxf(rm1, fmaxf(s[jn][2], s[jn][3]));
        }
        rm0 = fmaxf(rm0, __shfl_xor_sync(0xffffffffu, rm0, 1));
        rm0 = fmaxf(rm0, __shfl_xor_sync(0xffffffffu, rm0, 2));
        rm1 = fmaxf(rm1, __shfl_xor_sync(0xffffffffu, rm1, 1));
        rm1 = fmaxf(rm1, __shfl_xor_sync(0xffffffffu, rm1, 2));
        if (rm0 > m0r) {
            float sc0 = __expf(m0r - rm0);
            m0r = rm0; m0s = rm0 * LOG2E;
            lsA[0] *= sc0; lsA[1] *= sc0;
            #pragma unroll
            for (int i = 0; i < 8; i++) { o[i][0] *= sc0; o[i][1] *= sc0; }
        }
        if (rm1 > m1r) {
            float sc1 = __expf(m1r - rm1);
            m1r = rm1; m1s = rm1 * LOG2E;
            lsA[2] *= sc1; lsA[3] *= sc1;
            #pragma unroll
            for (int i = 0; i < 8; i++) { o[i][2] *= sc1; o[i][3] *= sc1; }
        }

        // ---- P = exp2(s*log2e - m*log2e) via ex2.approx.f16x2 ----
        uint32_t pa[4][4];
        #pragma unroll
        for (int jn = 0; jn < 8; jn++) {
            float t0 = fmaf(s[jn][0], LOG2E, -m0s);
            float t1 = fmaf(s[jn][1], LOG2E, -m0s);
            float t2 = fmaf(s[jn][2], LOG2E, -m1s);
            float t3 = fmaf(s[jn][3], LOG2E, -m1s);
            int kj = jn >> 1, base = (jn & 1) * 2;
            pa[kj][base + 0] = ex2_f16x2(cvt_f16x2(t0, t1));
            pa[kj][base + 1] = ex2_f16x2(cvt_f16x2(t2, t3));
        }

        // ---- lsum += row-sums of P (ones column) ----
        #pragma unroll
        for (int kj = 0; kj < 4; kj++)
            mma16816(lsA, pa[kj], bones);

        // ---- O += P V (1 term) ----
        #pragma unroll
        for (int kj = 0; kj < 4; kj++) {
            #pragma unroll
            for (int pd = 0; pd < 4; pd++) {
                uint32_t bv[4];
                uint32_t va = (uint32_t)((kj * 16 + ((l >> 3) & 1) * 8 + (l & 7)) * 144
                                         + (pd * 16 + ((l >> 4) & 1) * 8) * 2);
                ldsm4t(bv, sV + va);
                #pragma unroll
                for (int q = 0; q < 2; q++)
                    mma16816(o[pd * 2 + q], pa[kj], bv + q * 2);
            }
        }
    }

    float ls0 = __shfl_sync(0xffffffffu, lsA[0], l & 28);
    float ls1 = __shfl_sync(0xffffffffu, lsA[2], l & 28);
    float inv0 = 1.f / ls0, inv1 = 1.f / ls1;

    const int rowg = b * N_ + q0 + w * 16 + (l >> 2);
    #pragma unroll
    for (int dn = 0; dn < 8; dn++) {
        int cc = h * 64 + dn * 8 + (l & 3) * 2;
        uint32_t h0, l0, h1, l1;
        split2h(o[dn][0] * inv0, o[dn][1] * inv0, h0, l0);
        split2h(o[dn][2] * inv1, o[dn][3] * inv1, h1, l1);
        *(uint32_t*)(AOhi + (size_t)rowg * 512 + cc)       = h0;
        *(uint32_t*)(AOlo + (size_t)rowg * 512 + cc)       = l0;
        *(uint32_t*)(AOhi + (size_t)(rowg + 8) * 512 + cc) = h1;
        *(uint32_t*)(AOlo + (size_t)(rowg + 8) * 512 + cc) = l1;
    }
}

// ---------------------------------------------------------------------------
extern "C" void kernel_launch(void* const* d_in, const int* in_sizes, int n_in,
                              void* d_out, int out_size)
{
    (void)in_sizes; (void)n_in; (void)out_size;
    const float* current = (const float*)d_in[0];
    const float* hidden  = (const float*)d_in[1];
    const float* Wq      = (const float*)d_in[2];
    const float* Wkv     = (const float*)d_in[3];
    const float* Wo      = (const float*)d_in[4];
    float* out           = (float*)d_out;

    __half *curhi, *curlo, *hidhi, *hidlo;
    __half *wqThi, *wqTlo, *wkvThi, *wkvTlo, *woT;
    __half *qhi, *qlo, *khi, *klo, *vv, *aohi, *aolo;
    cudaGetSymbolAddress((void**)&curhi, g_curhi); cudaGetSymbolAddress((void**)&curlo, g_curlo);
    cudaGetSymbolAddress((void**)&hidhi, g_hidhi); cudaGetSymbolAddress((void**)&hidlo, g_hidlo);
    cudaGetSymbolAddress((void**)&wqThi, g_wqThi); cudaGetSymbolAddress((void**)&wqTlo, g_wqTlo);
    cudaGetSymbolAddress((void**)&wkvThi, g_wkvThi); cudaGetSymbolAddress((void**)&wkvTlo, g_wkvTlo);
    cudaGetSymbolAddress((void**)&woT, g_woT);
    cudaGetSymbolAddress((void**)&qhi, g_qhi);   cudaGetSymbolAddress((void**)&qlo, g_qlo);
    cudaGetSymbolAddress((void**)&khi, g_khi);   cudaGetSymbolAddress((void**)&klo, g_klo);
    cudaGetSymbolAddress((void**)&vv,  g_v);
    cudaGetSymbolAddress((void**)&aohi, g_aohi); cudaGetSymbolAddress((void**)&aolo, g_aolo);

    const int gemm_smem = 2 * GSTG;                  // 81920
    const int attn_smem = 2 * GB + 2 * KVSTG;        // 92160 (occ 2: 184 KB OK)
    cudaFuncSetAttribute(proj_qkv, cudaFuncAttributeMaxDynamicSharedMemorySize, gemm_smem);
    cudaFuncSetAttribute(proj_out, cudaFuncAttributeMaxDynamicSharedMemorySize, gemm_smem);
    cudaFuncSetAttribute(attn_mma, cudaFuncAttributeMaxDynamicSharedMemorySize, attn_smem);

    const int n4 = MT_ * DM_ / 4;
    prep_all<<<8192 + 1024, 256>>>(current, hidden, Wq, Wkv, Wo,
                                   curhi, curlo, hidhi, hidlo,
                                   wqThi, wqTlo, wkvThi, wkvTlo, woT, n4);

    proj_qkv<<<dim3(12, 64), 256, gemm_smem>>>(curhi, curlo, hidhi, hidlo,
                                               wqThi, wqTlo, wkvThi, wkvTlo,
                                               qhi, qlo, khi, klo, vv);
    attn_mma<<<dim3(B_ * H_, N_ / 128), 256, attn_smem>>>(qhi, qlo, khi, klo, vv,
                                                          aohi, aolo);
    proj_out<<<dim3(4, 64), 256, gemm_smem>>>(aohi, aolo, woT, out);
}